// round 11
// baseline (speedup 1.0000x reference)
#include <cuda_runtime.h>
#include <cuda_bf16.h>
#include <math.h>
#include <stdint.h>

// ---------------- problem constants ----------------
#define BATCH   8
#define CDIM    192
#define HEADS   6
#define HD      32
#define NTOK    64
#define NWIN    512
#define ROWS    32768
#define CH3     576
#define FF      768
#define HW      4096
#define IMGW    64

// weight plane offsets (elements)
#define OFF_QKV  0
#define OFF_PROJ 110592
#define OFF_FC1  147456
#define OFF_FC2  294912
#define WTOT     442368

// ---------------- scratch ----------------
__device__ float g_S  [ROWS * (size_t)CDIM];   // LN1 fp32 (shortcut); reused as final token-major Y
__device__ float g_QKV[ROWS * (size_t)CH3];
__device__ float g_X2 [ROWS * (size_t)CDIM];

__device__ __nv_bfloat16 g_Sh[ROWS * (size_t)CDIM], g_Sl[ROWS * (size_t)CDIM];
__device__ __nv_bfloat16 g_Oh[ROWS * (size_t)CDIM], g_Ol[ROWS * (size_t)CDIM];
__device__ __nv_bfloat16 g_Nh[ROWS * (size_t)CDIM], g_Nl[ROWS * (size_t)CDIM];
__device__ __nv_bfloat16 g_Hh[ROWS * (size_t)FF],   g_Hl[ROWS * (size_t)FF];
__device__ __nv_bfloat16 g_Wh[WTOT], g_Wl[WTOT];

// ---------------- helpers ----------------
__device__ __forceinline__ uint32_t smem_to_u32(const void* p) {
    uint32_t a;
    asm("{ .reg .u64 t; cvta.to.shared.u64 t, %1; cvt.u32.u64 %0, t; }" : "=r"(a) : "l"(p));
    return a;
}
__device__ __forceinline__ void ldm4(uint32_t* r, uint32_t addr) {
    asm volatile("ldmatrix.sync.aligned.m8n8.x4.shared.b16 {%0,%1,%2,%3}, [%4];"
                 : "=r"(r[0]), "=r"(r[1]), "=r"(r[2]), "=r"(r[3]) : "r"(addr));
}
__device__ __forceinline__ void mma_bf16(float* c, const uint32_t* a, uint32_t b0, uint32_t b1) {
    asm volatile("mma.sync.aligned.m16n8k16.row.col.f32.bf16.bf16.f32 "
                 "{%0,%1,%2,%3}, {%4,%5,%6,%7}, {%8,%9}, {%0,%1,%2,%3};"
                 : "+f"(c[0]), "+f"(c[1]), "+f"(c[2]), "+f"(c[3])
                 : "r"(a[0]), "r"(a[1]), "r"(a[2]), "r"(a[3]), "r"(b0), "r"(b1));
}
__device__ __forceinline__ void splitf(float v, __nv_bfloat16& h, __nv_bfloat16& l) {
    h = __float2bfloat16(v);
    l = __float2bfloat16(v - __bfloat162float(h));
}
__device__ __forceinline__ void split_pair(float x, float y, unsigned& h, unsigned& l) {
    __nv_bfloat16 hx, lx, hy, ly;
    splitf(x, hx, lx);
    splitf(y, hy, ly);
    __nv_bfloat162 hh = __halves2bfloat162(hx, hy);
    __nv_bfloat162 ll = __halves2bfloat162(lx, ly);
    h = *reinterpret_cast<unsigned*>(&hh);
    l = *reinterpret_cast<unsigned*>(&ll);
}
// monotonic float->u32 key (order-preserving)
__device__ __forceinline__ unsigned fkey(float v) {
    unsigned u = __float_as_uint(v);
    return (u & 0x80000000u) ? ~u : (u | 0x80000000u);
}
__device__ __forceinline__ float unfkey(unsigned k) {
    return __uint_as_float((k & 0x80000000u) ? (k & 0x7fffffffu) : ~k);
}
#define CP16(sdst, gsrc) \
    asm volatile("cp.async.ca.shared.global [%0], [%1], 16;" :: "r"(sdst), "l"(gsrc) : "memory")
#define CP_COMMIT() asm volatile("cp.async.commit_group;" ::: "memory")

// ---- GEMM smem: BM=256 BN=64 BK=32, row stride 40 elems (80B, ldmatrix conflict-free) ----
#define AH_OFF 0        // 256*40*2 = 20480
#define AL_OFF 20480
#define BH_OFF 40960    // 64*40*2 = 5120
#define BL_OFF 46080
#define STG    51200
#define GSMEM  102400   // 2 stages; also covers 256x65 fp32 epilogue tile (66560)

// ---------------- bf16x3 HMMA GEMM, 256x64 CTA tile, 64x32 warp tile ----------------
// MODE 0: A=g_Sh/l, B=W[qkv]  -> g_QKV fp32                    (K=192, N=576)
// MODE 1: A=g_Oh/l, B=W[proj] -> g_X2 = g_S + .  fp32          (K=192, N=192)
// MODE 2: A=g_Nh/l, B=W[fc1]  -> g_Hh/l = split(gelu(.))       (K=192, N=768)
// MODE 3: A=g_Hh/l, B=W[fc2]  -> g_S (token-major) = g_X2 + .  (K=768, N=192)
template<int MODE, int K>
__global__ void __launch_bounds__(256)
gemm_mma(const float* __restrict__ bias) {
    extern __shared__ char sm[];
    uint32_t sb = smem_to_u32(sm);

    const __nv_bfloat16* Ah_g = (MODE == 0) ? g_Sh : (MODE == 1) ? g_Oh : (MODE == 2) ? g_Nh : g_Hh;
    const __nv_bfloat16* Al_g = (MODE == 0) ? g_Sl : (MODE == 1) ? g_Ol : (MODE == 2) ? g_Nl : g_Hl;
    constexpr int WOFF = (MODE == 0) ? OFF_QKV : (MODE == 1) ? OFF_PROJ : (MODE == 2) ? OFF_FC1 : OFF_FC2;
    const __nv_bfloat16* Bh_g = g_Wh + WOFF;
    const __nv_bfloat16* Bl_g = g_Wl + WOFF;

    int tid = threadIdx.x;
    int lane = tid & 31, w = tid >> 5;
    int wm = (w >> 1) * 64;     // 0,64,128,192
    int wn = (w & 1) * 32;      // 0,32
    int rbase = blockIdx.x * 256, cbase = blockIdx.y * 64;

    uint32_t aRow = (lane & 7) + ((lane >> 3) & 1) * 8;
    uint32_t aK   = (lane >> 4) * 8;
    uint32_t bN   = ((lane >> 4) & 1) * 8 + (lane & 7);
    uint32_t bK   = ((lane >> 3) & 1) * 8;

    float acc[4][4][4];
    #pragma unroll
    for (int mi = 0; mi < 4; mi++)
        #pragma unroll
        for (int ni = 0; ni < 4; ni++)
            #pragma unroll
            for (int j = 0; j < 4; j++) acc[mi][ni][j] = 0.f;

    auto copy_stage = [&](int st, int kt) {
        uint32_t base = sb + st * STG;
        // A: 256 rows x 4 groups of 8 elems -> 1024 groups; 4 per thread per plane
        #pragma unroll
        for (int i = 0; i < 4; i++) {
            int g = i * 256 + tid;
            int r = g >> 2, s2 = g & 3;
            size_t go = (size_t)(rbase + r) * K + kt + s2 * 8;
            uint32_t so = (uint32_t)(r * 40 + s2 * 8) * 2;
            CP16(base + AH_OFF + so, Ah_g + go);
            CP16(base + AL_OFF + so, Al_g + go);
        }
        // B: 64 rows x 4 groups -> 256 groups; 1 per thread per plane
        {
            int r = tid >> 2, s2 = tid & 3;
            size_t go = (size_t)(cbase + r) * K + kt + s2 * 8;
            uint32_t so = (uint32_t)(r * 40 + s2 * 8) * 2;
            CP16(base + BH_OFF + so, Bh_g + go);
            CP16(base + BL_OFF + so, Bl_g + go);
        }
        CP_COMMIT();
    };

    constexpr int NC = K / 32;
    copy_stage(0, 0);

    for (int c = 0; c < NC; c++) {
        if (c + 1 < NC) {
            copy_stage((c + 1) & 1, (c + 1) * 32);
            asm volatile("cp.async.wait_group 1;" ::: "memory");
        } else {
            asm volatile("cp.async.wait_group 0;" ::: "memory");
        }
        __syncthreads();

        uint32_t stb = sb + (c & 1) * STG;
        #pragma unroll
        for (int kk = 0; kk < 32; kk += 16) {
            uint32_t ah[4][4], al[4][4], bh[2][4], bl[2][4];
            #pragma unroll
            for (int p = 0; p < 2; p++) {
                uint32_t off = ((wn + p * 16 + bN) * 40 + kk + bK) * 2;
                ldm4(bh[p], stb + BH_OFF + off);
                ldm4(bl[p], stb + BL_OFF + off);
            }
            #pragma unroll
            for (int mi = 0; mi < 4; mi++) {
                uint32_t off = ((wm + mi * 16 + aRow) * 40 + kk + aK) * 2;
                ldm4(ah[mi], stb + AH_OFF + off);
                ldm4(al[mi], stb + AL_OFF + off);
            }
            #pragma unroll
            for (int mi = 0; mi < 4; mi++)
                #pragma unroll
                for (int ni = 0; ni < 4; ni++) {
                    int p = ni >> 1, o = (ni & 1) * 2;
                    mma_bf16(acc[mi][ni], ah[mi], bh[p][o], bh[p][o + 1]);
                    mma_bf16(acc[mi][ni], ah[mi], bl[p][o], bl[p][o + 1]);
                    mma_bf16(acc[mi][ni], al[mi], bh[p][o], bh[p][o + 1]);
                }
        }
        __syncthreads();
    }

    // ---- epilogue: frags -> smem fp32 tile (256x65) -> coalesced global ----
    float* st = reinterpret_cast<float*>(sm);
    #pragma unroll
    for (int mi = 0; mi < 4; mi++)
        #pragma unroll
        for (int ni = 0; ni < 4; ni++) {
            int row = wm + mi * 16 + (lane >> 2);
            int col = wn + ni * 8 + (lane & 3) * 2;
            st[row * 65 + col]           = acc[mi][ni][0];
            st[row * 65 + col + 1]       = acc[mi][ni][1];
            st[(row + 8) * 65 + col]     = acc[mi][ni][2];
            st[(row + 8) * 65 + col + 1] = acc[mi][ni][3];
        }
    __syncthreads();

    for (int i = tid; i < 256 * 64; i += 256) {
        int row = i >> 6, j = i & 63;
        int r = rbase + row, cc = cbase + j;
        float v = st[row * 65 + j] + bias[cc];
        if (MODE == 0) {
            g_QKV[(size_t)r * CH3 + cc] = v;
        } else if (MODE == 1) {
            g_X2[(size_t)r * CDIM + cc] = g_S[(size_t)r * CDIM + cc] + v;
        } else if (MODE == 2) {
            float a = 0.5f * v * (1.0f + erff(v * 0.70710678118654752f));
            __nv_bfloat16 hh, ll;
            splitf(a, hh, ll);
            g_Hh[(size_t)r * FF + cc] = hh;
            g_Hl[(size_t)r * FF + cc] = ll;
        } else {
            g_S[(size_t)r * CDIM + cc] = g_X2[(size_t)r * CDIM + cc] + v;
        }
    }
}

// ---------------- weight conversion ----------------
__global__ void __launch_bounds__(256)
wconv_kernel(const float* __restrict__ qkv_w, const float* __restrict__ proj_w,
             const float* __restrict__ fc1_w, const float* __restrict__ fc2_w) {
    int idx = blockIdx.x * 256 + threadIdx.x;
    if (idx >= WTOT / 4) return;
    int i4 = idx * 4;
    const float* src;
    int off;
    if (i4 < OFF_PROJ)      { src = qkv_w;  off = i4; }
    else if (i4 < OFF_FC1)  { src = proj_w; off = i4 - OFF_PROJ; }
    else if (i4 < OFF_FC2)  { src = fc1_w;  off = i4 - OFF_FC1; }
    else                    { src = fc2_w;  off = i4 - OFF_FC2; }
    float4 v = *reinterpret_cast<const float4*>(src + off);
    __nv_bfloat16 h[4], l[4];
    splitf(v.x, h[0], l[0]); splitf(v.y, h[1], l[1]);
    splitf(v.z, h[2], l[2]); splitf(v.w, h[3], l[3]);
    *reinterpret_cast<uint2*>(g_Wh + i4) = *reinterpret_cast<uint2*>(h);
    *reinterpret_cast<uint2*>(g_Wl + i4) = *reinterpret_cast<uint2*>(l);
}

// ---------------- LN1 + window partition ----------------
__global__ void __launch_bounds__(256)
ln1_kernel(const float* __restrict__ x, const float* __restrict__ g,
           const float* __restrict__ b) {
    extern __shared__ float smf[];
    float* tile = smf;
    float* smu  = smf + 64 * 193;
    float* srs  = smu + 64;

    int win = blockIdx.x;
    int bi = win >> 6, wy = (win >> 3) & 7, wx = win & 7;
    const float* xb = x + (size_t)bi * CDIM * HW;

    for (int i = threadIdx.x; i < NTOK * CDIM; i += blockDim.x) {
        int c = i >> 6, n = i & 63;
        int iy = n >> 3, ix = n & 7;
        int hw = ((wy << 3) + iy) * IMGW + (wx << 3) + ix;
        tile[n * 193 + c] = xb[(size_t)c * HW + hw];
    }
    __syncthreads();
    if (threadIdx.x < NTOK) {
        int n = threadIdx.x;
        float s = 0.f, ss = 0.f;
        #pragma unroll 4
        for (int c = 0; c < CDIM; c++) {
            float v = tile[n * 193 + c];
            s += v; ss += v * v;
        }
        float mu = s * (1.0f / CDIM);
        float var = ss * (1.0f / CDIM) - mu * mu;
        smu[n] = mu;
        srs[n] = rsqrtf(fmaxf(var, 0.f) + 1e-5f);
    }
    __syncthreads();
    size_t ob = (size_t)win * NTOK * CDIM;
    for (int i = threadIdx.x; i < NTOK * CDIM; i += blockDim.x) {
        int n = i / CDIM, c = i - n * CDIM;
        float v = (tile[n * 193 + c] - smu[n]) * srs[n] * g[c] + b[c];
        g_S[ob + i] = v;
        __nv_bfloat16 hh, ll;
        splitf(v, hh, ll);
        g_Sh[ob + i] = hh;
        g_Sl[ob + i] = ll;
    }
}

// ---------------- LN2 normalize -> planes ----------------
__global__ void __launch_bounds__(256)
ln2_norm_kernel(const float* __restrict__ g, const float* __restrict__ b) {
    int r = blockIdx.x * 8 + (threadIdx.x >> 5);
    int lane = threadIdx.x & 31;
    const float* row = g_X2 + (size_t)r * CDIM;
    float2 v[3];
    float s = 0.f, ss = 0.f;
    #pragma unroll
    for (int i = 0; i < 3; i++) {
        v[i] = *reinterpret_cast<const float2*>(row + i * 64 + lane * 2);
        s += v[i].x + v[i].y;
        ss += v[i].x * v[i].x + v[i].y * v[i].y;
    }
    #pragma unroll
    for (int o = 16; o > 0; o >>= 1) {
        s  += __shfl_xor_sync(0xffffffffu, s,  o);
        ss += __shfl_xor_sync(0xffffffffu, ss, o);
    }
    float mu = s * (1.0f / CDIM);
    float var = ss * (1.0f / CDIM) - mu * mu;
    float rs = rsqrtf(fmaxf(var, 0.f) + 1e-5f);
    #pragma unroll
    for (int i = 0; i < 3; i++) {
        int c = i * 64 + lane * 2;
        float2 gg = *reinterpret_cast<const float2*>(g + c);
        float2 bb = *reinterpret_cast<const float2*>(b + c);
        float vx = (v[i].x - mu) * rs * gg.x + bb.x;
        float vy = (v[i].y - mu) * rs * gg.y + bb.y;
        unsigned hp, lp;
        split_pair(vx, vy, hp, lp);
        *reinterpret_cast<unsigned*>(g_Nh + (size_t)r * CDIM + c) = hp;
        *reinterpret_cast<unsigned*>(g_Nl + (size_t)r * CDIM + c) = lp;
    }
}

// ---------------- attention: HMMA logits/AV + redux topk ----------------
#define A_QH  0        // 64*40*2 = 5120   (later aliased by PH/PL)
#define A_QL  5120
#define A_KH  10240
#define A_KL  15360
#define A_PH  0        // 64*72*2 = 9216
#define A_PL  9216
#define A_VTH 20480    // 32*72*2 = 4608
#define A_VTL 25088
#define A_SA  29696    // 64*65*4 = 16640 fp32  (aliased by s_v staging 64*37*4)
#define A_SV  29696
#define A_ST  46336    // 225*4
#define ATTN_SMEM 47296

__global__ void __launch_bounds__(256)
attn_kernel(const float* __restrict__ rpb, const float* __restrict__ temp) {
    extern __shared__ char smc[];
    uint32_t sb = smem_to_u32(smc);
    __nv_bfloat16* qh = reinterpret_cast<__nv_bfloat16*>(smc + A_QH);
    __nv_bfloat16* ql = reinterpret_cast<__nv_bfloat16*>(smc + A_QL);
    __nv_bfloat16* kh = reinterpret_cast<__nv_bfloat16*>(smc + A_KH);
    __nv_bfloat16* kl = reinterpret_cast<__nv_bfloat16*>(smc + A_KL);
    __nv_bfloat16* ph = reinterpret_cast<__nv_bfloat16*>(smc + A_PH);
    __nv_bfloat16* pl = reinterpret_cast<__nv_bfloat16*>(smc + A_PL);
    float* s_a = reinterpret_cast<float*>(smc + A_SA);
    float* s_v = reinterpret_cast<float*>(smc + A_SV);
    float* s_t = reinterpret_cast<float*>(smc + A_ST);

    int blk = blockIdx.x;
    int win = blk / HEADS;
    int h = blk - win * HEADS;
    int tid = threadIdx.x, lane = tid & 31, w = tid >> 5;
    size_t base = (size_t)win * NTOK;
    float tmp = temp[h];

    for (int i = tid; i < 225; i += 256) s_t[i] = rpb[i * HEADS + h];

    uint32_t aRow = lane & 15;
    uint32_t aK   = (lane >> 4) * 8;
    uint32_t bN   = ((lane >> 4) & 1) * 8 + (lane & 7);
    uint32_t bK   = ((lane >> 3) & 1) * 8;

    // ---- phase 1: load + l2norm q,k -> planes; v -> fp32 staging ----
    for (int n = w; n < NTOK; n += 8) {
        const float* qp = g_QKV + (base + n) * CH3 + h * HD;
        float qv = qp[lane], kv = qp[192 + lane], vv = qp[384 + lane];
        float qs = qv * qv, ks = kv * kv;
        #pragma unroll
        for (int o = 16; o > 0; o >>= 1) {
            qs += __shfl_xor_sync(0xffffffffu, qs, o);
            ks += __shfl_xor_sync(0xffffffffu, ks, o);
        }
        float qn = qv * (tmp / fmaxf(sqrtf(qs), 1e-12f));
        float kn = kv / fmaxf(sqrtf(ks), 1e-12f);
        __nv_bfloat16 hh, ll;
        splitf(qn, hh, ll);
        qh[n * 40 + lane] = hh; ql[n * 40 + lane] = ll;
        splitf(kn, hh, ll);
        kh[n * 40 + lane] = hh; kl[n * 40 + lane] = ll;
        s_v[n * 37 + lane] = vv;
    }
    __syncthreads();

    // ---- phase 2: transposed V planes (d-major, stride 72) ----
    {
        int d = tid >> 3, m0 = (tid & 7) * 8;
        #pragma unroll
        for (int i = 0; i < 4; i++) {
            float a = s_v[(m0 + 2 * i) * 37 + d];
            float b = s_v[(m0 + 2 * i + 1) * 37 + d];
            unsigned hp, lp;
            split_pair(a, b, hp, lp);
            reinterpret_cast<unsigned*>(smc + A_VTH)[d * 36 + m0 / 2 + i] = hp;
            reinterpret_cast<unsigned*>(smc + A_VTL)[d * 36 + m0 / 2 + i] = lp;
        }
    }
    __syncthreads();

    // ---- phase 3: logits MMA (64x64x32, bf16x3) -> s_a fp32 ----
    {
        int mw = w & 1, nw = w >> 1;
        float c[2][2][4];
        #pragma unroll
        for (int mi = 0; mi < 2; mi++)
            #pragma unroll
            for (int nj = 0; nj < 2; nj++)
                #pragma unroll
                for (int j = 0; j < 4; j++) c[mi][nj][j] = 0.f;
        #pragma unroll
        for (int kk = 0; kk < 32; kk += 16) {
            uint32_t ah[2][4], al[2][4], bh[4], bl[4];
            #pragma unroll
            for (int mi = 0; mi < 2; mi++) {
                uint32_t off = ((mw * 32 + mi * 16 + aRow) * 40 + kk + aK) * 2;
                ldm4(ah[mi], sb + A_QH + off);
                ldm4(al[mi], sb + A_QL + off);
            }
            uint32_t boff = ((nw * 16 + bN) * 40 + kk + bK) * 2;
            ldm4(bh, sb + A_KH + boff);
            ldm4(bl, sb + A_KL + boff);
            #pragma unroll
            for (int mi = 0; mi < 2; mi++)
                #pragma unroll
                for (int nj = 0; nj < 2; nj++) {
                    mma_bf16(c[mi][nj], ah[mi], bh[2 * nj], bh[2 * nj + 1]);
                    mma_bf16(c[mi][nj], ah[mi], bl[2 * nj], bl[2 * nj + 1]);
                    mma_bf16(c[mi][nj], al[mi], bh[2 * nj], bh[2 * nj + 1]);
                }
        }
        #pragma unroll
        for (int mi = 0; mi < 2; mi++)
            #pragma unroll
            for (int nj = 0; nj < 2; nj++) {
                int r = mw * 32 + mi * 16 + (lane >> 2);
                int cc = nw * 16 + nj * 8 + (lane & 3) * 2;
                s_a[r * 65 + cc]           = c[mi][nj][0];
                s_a[r * 65 + cc + 1]       = c[mi][nj][1];
                s_a[(r + 8) * 65 + cc]     = c[mi][nj][2];
                s_a[(r + 8) * 65 + cc + 1] = c[mi][nj][3];
            }
    }
    __syncthreads();

    // ---- phase 4: top-16 (redux removal, distinct-value fast path) + rpb + softmax ----
    {
        int jy0 = lane >> 3, jx0 = lane & 7;
        int jy1 = (lane + 32) >> 3, jx1 = lane & 7;
        for (int pr = w; pr < 32; pr += 8) {
            int na = pr * 2, nb = na + 1;
            float ra0 = s_a[na * 65 + lane], ra1 = s_a[na * 65 + 32 + lane];
            float rb0 = s_a[nb * 65 + lane], rb1 = s_a[nb * 65 + 32 + lane];
            unsigned oa0 = fkey(ra0), oa1 = fkey(ra1);
            unsigned ob0 = fkey(rb0), ob1 = fkey(rb1);
            unsigned ka0 = oa0, ka1 = oa1, kb0 = ob0, kb1 = ob1;
            // values are distinct w.p. ~1: zero the (unique) slot equal to the max
            #pragma unroll 1
            for (int it = 0; it < 15; it++) {
                unsigned ma = __reduce_max_sync(0xffffffffu, ka0 > ka1 ? ka0 : ka1);
                unsigned mb = __reduce_max_sync(0xffffffffu, kb0 > kb1 ? kb0 : kb1);
                if (ka0 == ma) ka0 = 0u; else if (ka1 == ma) ka1 = 0u;
                if (kb0 == mb) kb0 = 0u; else if (kb1 == mb) kb1 = 0u;
            }
            unsigned kta = __reduce_max_sync(0xffffffffu, ka0 > ka1 ? ka0 : ka1);
            unsigned ktb = __reduce_max_sync(0xffffffffu, kb0 > kb1 ? kb0 : kb1);

            int iya = na >> 3, ixa = na & 7;
            int iyb = nb >> 3, ixb = nb & 7;
            float ea0 = ((oa0 >= kta) ? ra0 : -100.0f) + s_t[(iya - jy0 + 7) * 15 + (ixa - jx0 + 7)];
            float ea1 = ((oa1 >= kta) ? ra1 : -100.0f) + s_t[(iya - jy1 + 7) * 15 + (ixa - jx1 + 7)];
            float eb0 = ((ob0 >= ktb) ? rb0 : -100.0f) + s_t[(iyb - jy0 + 7) * 15 + (ixb - jx0 + 7)];
            float eb1 = ((ob1 >= ktb) ? rb1 : -100.0f) + s_t[(iyb - jy1 + 7) * 15 + (ixb - jx1 + 7)];

            unsigned mka = __reduce_max_sync(0xffffffffu, fkey(fmaxf(ea0, ea1)));
            unsigned mkb = __reduce_max_sync(0xffffffffu, fkey(fmaxf(eb0, eb1)));
            float mxa = unfkey(mka), mxb = unfkey(mkb);
            float pa0 = expf(ea0 - mxa), pa1 = expf(ea1 - mxa);
            float pb0 = expf(eb0 - mxb), pb1 = expf(eb1 - mxb);
            float sa = pa0 + pa1, sbm = pb0 + pb1;
            #pragma unroll
            for (int o = 16; o > 0; o >>= 1) {
                sa  += __shfl_xor_sync(0xffffffffu, sa,  o);
                sbm += __shfl_xor_sync(0xffffffffu, sbm, o);
            }
            float ia = 1.0f / sa, ib = 1.0f / sbm;
            __nv_bfloat16 hh, ll;
            splitf(pa0 * ia, hh, ll); ph[na * 72 + lane] = hh;      pl[na * 72 + lane] = ll;
            splitf(pa1 * ia, hh, ll); ph[na * 72 + 32 + lane] = hh; pl[na * 72 + 32 + lane] = ll;
            splitf(pb0 * ib, hh, ll); ph[nb * 72 + lane] = hh;      pl[nb * 72 + lane] = ll;
            splitf(pb1 * ib, hh, ll); ph[nb * 72 + 32 + lane] = hh; pl[nb * 72 + 32 + lane] = ll;
        }
    }
    __syncthreads();

    // ---- phase 5: AV MMA (64x32x64, bf16x3) -> g_Oh/g_Ol ----
    {
        int mw = w >> 1, dw = w & 1;
        float c[2][4];
        #pragma unroll
        for (int nj = 0; nj < 2; nj++)
            #pragma unroll
            for (int j = 0; j < 4; j++) c[nj][j] = 0.f;
        #pragma unroll
        for (int kk = 0; kk < 64; kk += 16) {
            uint32_t ahh[4], all[4], bh[4], bl[4];
            uint32_t aoff = ((mw * 16 + aRow) * 72 + kk + aK) * 2;
            ldm4(ahh, sb + A_PH + aoff);
            ldm4(all, sb + A_PL + aoff);
            uint32_t boff = ((dw * 16 + bN) * 72 + kk + bK) * 2;
            ldm4(bh, sb + A_VTH + boff);
            ldm4(bl, sb + A_VTL + boff);
            #pragma unroll
            for (int nj = 0; nj < 2; nj++) {
                mma_bf16(c[nj], ahh, bh[2 * nj], bh[2 * nj + 1]);
                mma_bf16(c[nj], ahh, bl[2 * nj], bl[2 * nj + 1]);
                mma_bf16(c[nj], all, bh[2 * nj], bh[2 * nj + 1]);
            }
        }
        #pragma unroll
        for (int nj = 0; nj < 2; nj++) {
            int r0 = mw * 16 + (lane >> 2);
            int dloc = dw * 16 + nj * 8 + (lane & 3) * 2;
            size_t o0 = (base + r0) * CDIM + h * HD + dloc;
            size_t o1 = (base + r0 + 8) * CDIM + h * HD + dloc;
            unsigned hp, lp;
            split_pair(c[nj][0], c[nj][1], hp, lp);
            *reinterpret_cast<unsigned*>(g_Oh + o0) = hp;
            *reinterpret_cast<unsigned*>(g_Ol + o0) = lp;
            split_pair(c[nj][2], c[nj][3], hp, lp);
            *reinterpret_cast<unsigned*>(g_Oh + o1) = hp;
            *reinterpret_cast<unsigned*>(g_Ol + o1) = lp;
        }
    }
}

// ---------------- final transpose: g_S (token-major Y) -> NCHW out ----------------
__global__ void __launch_bounds__(256)
out_tr_kernel(float* __restrict__ out) {
    extern __shared__ float smf[];
    float* tile = smf;  // 64 x 193
    int win = blockIdx.x;
    int bi = win >> 6, wy = (win >> 3) & 7, wx = win & 7;
    const float* src = g_S + (size_t)win * NTOK * CDIM;
    for (int i = threadIdx.x; i < NTOK * CDIM; i += 256) {
        int n = i / CDIM, c = i - n * CDIM;
        tile[n * 193 + c] = src[i];
    }
    __syncthreads();
    float* ob = out + (size_t)bi * CDIM * HW;
    for (int i = threadIdx.x; i < NTOK * CDIM; i += 256) {
        int c = i >> 6, n = i & 63;
        int iy = n >> 3, ix = n & 7;
        int hw = ((wy << 3) + iy) * IMGW + (wx << 3) + ix;
        ob[(size_t)c * HW + hw] = tile[n * 193 + c];
    }
}

// ---------------- launch ----------------
extern "C" void kernel_launch(void* const* d_in, const int* in_sizes, int n_in,
                              void* d_out, int out_size) {
    const float* x      = (const float*)d_in[0];
    const float* n1g    = (const float*)d_in[1];
    const float* n1b    = (const float*)d_in[2];
    const float* qkv_w  = (const float*)d_in[3];
    const float* qkv_b  = (const float*)d_in[4];
    const float* proj_w = (const float*)d_in[5];
    const float* proj_b = (const float*)d_in[6];
    const float* rpb    = (const float*)d_in[7];
    const float* temp   = (const float*)d_in[8];
    const float* n2g    = (const float*)d_in[9];
    const float* n2b    = (const float*)d_in[10];
    const float* fc1_w  = (const float*)d_in[11];
    const float* fc1_b  = (const float*)d_in[12];
    const float* fc2_w  = (const float*)d_in[13];
    const float* fc2_b  = (const float*)d_in[14];
    float* out = (float*)d_out;

    const int LN1_SMEM  = (64 * 193 + 128) * 4;
    const int TR_SMEM   = 64 * 193 * 4;
    cudaFuncSetAttribute(ln1_kernel,    cudaFuncAttributeMaxDynamicSharedMemorySize, LN1_SMEM);
    cudaFuncSetAttribute(attn_kernel,   cudaFuncAttributeMaxDynamicSharedMemorySize, ATTN_SMEM);
    cudaFuncSetAttribute(out_tr_kernel, cudaFuncAttributeMaxDynamicSharedMemorySize, TR_SMEM);
    cudaFuncSetAttribute(gemm_mma<0, 192>, cudaFuncAttributeMaxDynamicSharedMemorySize, GSMEM);
    cudaFuncSetAttribute(gemm_mma<1, 192>, cudaFuncAttributeMaxDynamicSharedMemorySize, GSMEM);
    cudaFuncSetAttribute(gemm_mma<2, 192>, cudaFuncAttributeMaxDynamicSharedMemorySize, GSMEM);
    cudaFuncSetAttribute(gemm_mma<3, 768>, cudaFuncAttributeMaxDynamicSharedMemorySize, GSMEM);

    wconv_kernel<<<(WTOT / 4 + 255) / 256, 256>>>(qkv_w, proj_w, fc1_w, fc2_w);
    ln1_kernel<<<NWIN, 256, LN1_SMEM>>>(x, n1g, n1b);
    gemm_mma<0, 192><<<dim3(ROWS / 256, CH3 / 64), 256, GSMEM>>>(qkv_b);
    attn_kernel<<<NWIN * HEADS, 256, ATTN_SMEM>>>(rpb, temp);
    gemm_mma<1, 192><<<dim3(ROWS / 256, CDIM / 64), 256, GSMEM>>>(proj_b);
    ln2_norm_kernel<<<ROWS / 8, 256>>>(n2g, n2b);
    gemm_mma<2, 192><<<dim3(ROWS / 256, FF / 64), 256, GSMEM>>>(fc1_b);
    gemm_mma<3, 768><<<dim3(ROWS / 256, CDIM / 64), 256, GSMEM>>>(fc2_b);
    out_tr_kernel<<<NWIN, 256, TR_SMEM>>>(out);
}

// round 13
// speedup vs baseline: 1.1001x; 1.1001x over previous
#include <cuda_runtime.h>
#include <cuda_bf16.h>
#include <math.h>
#include <stdint.h>

// ---------------- problem constants ----------------
#define BATCH   8
#define CDIM    192
#define HEADS   6
#define HD      32
#define NTOK    64
#define NWIN    512
#define ROWS    32768
#define CH3     576
#define FF      768
#define HW      4096
#define IMGW    64

// weight plane offsets (elements)
#define OFF_QKV  0
#define OFF_PROJ 110592
#define OFF_FC1  147456
#define OFF_FC2  294912
#define WTOT     442368

// ---------------- scratch ----------------
__device__ float g_S  [ROWS * (size_t)CDIM];   // LN1 fp32 (shortcut); reused as final token-major Y
__device__ float g_QKV[ROWS * (size_t)CH3];
__device__ float g_X2 [ROWS * (size_t)CDIM];

__device__ __nv_bfloat16 g_Sh[ROWS * (size_t)CDIM], g_Sl[ROWS * (size_t)CDIM];
__device__ __nv_bfloat16 g_Oh[ROWS * (size_t)CDIM], g_Ol[ROWS * (size_t)CDIM];
__device__ __nv_bfloat16 g_Nh[ROWS * (size_t)CDIM], g_Nl[ROWS * (size_t)CDIM];
__device__ __nv_bfloat16 g_Hh[ROWS * (size_t)FF],   g_Hl[ROWS * (size_t)FF];
__device__ __nv_bfloat16 g_Wh[WTOT], g_Wl[WTOT];

// ---------------- helpers ----------------
__device__ __forceinline__ uint32_t smem_to_u32(const void* p) {
    uint32_t a;
    asm("{ .reg .u64 t; cvta.to.shared.u64 t, %1; cvt.u32.u64 %0, t; }" : "=r"(a) : "l"(p));
    return a;
}
__device__ __forceinline__ void ldm4(uint32_t* r, uint32_t addr) {
    asm volatile("ldmatrix.sync.aligned.m8n8.x4.shared.b16 {%0,%1,%2,%3}, [%4];"
                 : "=r"(r[0]), "=r"(r[1]), "=r"(r[2]), "=r"(r[3]) : "r"(addr));
}
__device__ __forceinline__ void mma_bf16(float* c, const uint32_t* a, uint32_t b0, uint32_t b1) {
    asm volatile("mma.sync.aligned.m16n8k16.row.col.f32.bf16.bf16.f32 "
                 "{%0,%1,%2,%3}, {%4,%5,%6,%7}, {%8,%9}, {%0,%1,%2,%3};"
                 : "+f"(c[0]), "+f"(c[1]), "+f"(c[2]), "+f"(c[3])
                 : "r"(a[0]), "r"(a[1]), "r"(a[2]), "r"(a[3]), "r"(b0), "r"(b1));
}
__device__ __forceinline__ void splitf(float v, __nv_bfloat16& h, __nv_bfloat16& l) {
    h = __float2bfloat16(v);
    l = __float2bfloat16(v - __bfloat162float(h));
}
__device__ __forceinline__ void split_pair(float x, float y, unsigned& h, unsigned& l) {
    __nv_bfloat16 hx, lx, hy, ly;
    splitf(x, hx, lx);
    splitf(y, hy, ly);
    __nv_bfloat162 hh = __halves2bfloat162(hx, hy);
    __nv_bfloat162 ll = __halves2bfloat162(lx, ly);
    h = *reinterpret_cast<unsigned*>(&hh);
    l = *reinterpret_cast<unsigned*>(&ll);
}
// monotonic float->u32 key (order-preserving)
__device__ __forceinline__ unsigned fkey(float v) {
    unsigned u = __float_as_uint(v);
    return (u & 0x80000000u) ? ~u : (u | 0x80000000u);
}
__device__ __forceinline__ float unfkey(unsigned k) {
    return __uint_as_float((k & 0x80000000u) ? (k & 0x7fffffffu) : ~k);
}
#define CP16(sdst, gsrc) \
    asm volatile("cp.async.ca.shared.global [%0], [%1], 16;" :: "r"(sdst), "l"(gsrc) : "memory")
#define CP_COMMIT() asm volatile("cp.async.commit_group;" ::: "memory")

// ---- GEMM smem: BM=128 BN=96 BK=32, row stride 40 elems (80B, ldmatrix conflict-free) ----
#define AH_OFF 0        // 128*40*2 = 10240
#define AL_OFF 10240
#define BH_OFF 20480    // 96*40*2 = 7680
#define BL_OFF 28160
#define STG    35840
#define GSMEM  71680    // 2 stages; also covers 128x97 fp32 epilogue tile (49664)
#define GTHREADS 192

// ---------------- bf16x3 HMMA GEMM, 128x96 CTA tile, 64x32 warp tile (2m x 3n) ----------------
// MODE 0: A=g_Sh/l, B=W[qkv]  -> g_QKV fp32                    (K=192, N=576)
// MODE 1: A=g_Oh/l, B=W[proj] -> g_X2 = g_S + .  fp32          (K=192, N=192)
// MODE 2: A=g_Nh/l, B=W[fc1]  -> g_Hh/l = split(gelu(.))       (K=192, N=768)
// MODE 3: A=g_Hh/l, B=W[fc2]  -> g_S (token-major) = g_X2 + .  (K=768, N=192)
template<int MODE, int K>
__global__ void __launch_bounds__(GTHREADS)
gemm_mma(const float* __restrict__ bias) {
    extern __shared__ char sm[];
    uint32_t sb = smem_to_u32(sm);

    const __nv_bfloat16* Ah_g = (MODE == 0) ? g_Sh : (MODE == 1) ? g_Oh : (MODE == 2) ? g_Nh : g_Hh;
    const __nv_bfloat16* Al_g = (MODE == 0) ? g_Sl : (MODE == 1) ? g_Ol : (MODE == 2) ? g_Nl : g_Hl;
    constexpr int WOFF = (MODE == 0) ? OFF_QKV : (MODE == 1) ? OFF_PROJ : (MODE == 2) ? OFF_FC1 : OFF_FC2;
    const __nv_bfloat16* Bh_g = g_Wh + WOFF;
    const __nv_bfloat16* Bl_g = g_Wl + WOFF;

    int tid = threadIdx.x;
    int lane = tid & 31, w = tid >> 5;            // 6 warps
    int wm = (w >= 3) ? 64 : 0;                   // 2 m positions (64 rows each)
    int wn = (w % 3) * 32;                        // 3 n positions (32 cols each)
    int rbase = blockIdx.x * 128, cbase = blockIdx.y * 96;

    uint32_t aRow = (lane & 7) + ((lane >> 3) & 1) * 8;
    uint32_t aK   = (lane >> 4) * 8;
    uint32_t bN   = ((lane >> 4) & 1) * 8 + (lane & 7);
    uint32_t bK   = ((lane >> 3) & 1) * 8;

    float acc[4][4][4];
    #pragma unroll
    for (int mi = 0; mi < 4; mi++)
        #pragma unroll
        for (int ni = 0; ni < 4; ni++)
            #pragma unroll
            for (int j = 0; j < 4; j++) acc[mi][ni][j] = 0.f;

    auto copy_stage = [&](int st, int kt) {
        uint32_t base = sb + st * STG;
        // A: 128 rows x 4 kgroups (8 elems) = 512 tasks
        for (int g = tid; g < 512; g += GTHREADS) {
            int r = g >> 2, s2 = g & 3;
            size_t go = (size_t)(rbase + r) * K + kt + s2 * 8;
            uint32_t so = (uint32_t)(r * 40 + s2 * 8) * 2;
            CP16(base + AH_OFF + so, Ah_g + go);
            CP16(base + AL_OFF + so, Al_g + go);
        }
        // B: 96 rows x 4 kgroups = 384 tasks
        for (int g = tid; g < 384; g += GTHREADS) {
            int r = g >> 2, s2 = g & 3;
            size_t go = (size_t)(cbase + r) * K + kt + s2 * 8;
            uint32_t so = (uint32_t)(r * 40 + s2 * 8) * 2;
            CP16(base + BH_OFF + so, Bh_g + go);
            CP16(base + BL_OFF + so, Bl_g + go);
        }
        CP_COMMIT();
    };

    constexpr int NC = K / 32;
    copy_stage(0, 0);

    for (int c = 0; c < NC; c++) {
        if (c + 1 < NC) {
            copy_stage((c + 1) & 1, (c + 1) * 32);
            asm volatile("cp.async.wait_group 1;" ::: "memory");
        } else {
            asm volatile("cp.async.wait_group 0;" ::: "memory");
        }
        __syncthreads();

        uint32_t stb = sb + (c & 1) * STG;
        #pragma unroll
        for (int kk = 0; kk < 32; kk += 16) {
            uint32_t ah[4][4], al[4][4], bh[2][4], bl[2][4];
            #pragma unroll
            for (int p = 0; p < 2; p++) {
                uint32_t off = ((wn + p * 16 + bN) * 40 + kk + bK) * 2;
                ldm4(bh[p], stb + BH_OFF + off);
                ldm4(bl[p], stb + BL_OFF + off);
            }
            #pragma unroll
            for (int mi = 0; mi < 4; mi++) {
                uint32_t off = ((wm + mi * 16 + aRow) * 40 + kk + aK) * 2;
                ldm4(ah[mi], stb + AH_OFF + off);
                ldm4(al[mi], stb + AL_OFF + off);
            }
            #pragma unroll
            for (int mi = 0; mi < 4; mi++)
                #pragma unroll
                for (int ni = 0; ni < 4; ni++) {
                    int p = ni >> 1, o = (ni & 1) * 2;
                    mma_bf16(acc[mi][ni], ah[mi], bh[p][o], bh[p][o + 1]);
                    mma_bf16(acc[mi][ni], ah[mi], bl[p][o], bl[p][o + 1]);
                    mma_bf16(acc[mi][ni], al[mi], bh[p][o], bh[p][o + 1]);
                }
        }
        __syncthreads();
    }

    // ---- epilogue: frags -> smem fp32 tile (128x97) -> coalesced global ----
    float* st = reinterpret_cast<float*>(sm);
    #pragma unroll
    for (int mi = 0; mi < 4; mi++)
        #pragma unroll
        for (int ni = 0; ni < 4; ni++) {
            int row = wm + mi * 16 + (lane >> 2);
            int col = wn + ni * 8 + (lane & 3) * 2;
            st[row * 97 + col]           = acc[mi][ni][0];
            st[row * 97 + col + 1]       = acc[mi][ni][1];
            st[(row + 8) * 97 + col]     = acc[mi][ni][2];
            st[(row + 8) * 97 + col + 1] = acc[mi][ni][3];
        }
    __syncthreads();

    for (int i = tid; i < 128 * 96; i += GTHREADS) {
        int row = i / 96, j = i - row * 96;
        int r = rbase + row, cc = cbase + j;
        float v = st[row * 97 + j] + bias[cc];
        if (MODE == 0) {
            g_QKV[(size_t)r * CH3 + cc] = v;
        } else if (MODE == 1) {
            g_X2[(size_t)r * CDIM + cc] = g_S[(size_t)r * CDIM + cc] + v;
        } else if (MODE == 2) {
            float a = 0.5f * v * (1.0f + erff(v * 0.70710678118654752f));
            __nv_bfloat16 hh, ll;
            splitf(a, hh, ll);
            g_Hh[(size_t)r * FF + cc] = hh;
            g_Hl[(size_t)r * FF + cc] = ll;
        } else {
            g_S[(size_t)r * CDIM + cc] = g_X2[(size_t)r * CDIM + cc] + v;
        }
    }
}

// ---------------- weight conversion ----------------
__global__ void __launch_bounds__(256)
wconv_kernel(const float* __restrict__ qkv_w, const float* __restrict__ proj_w,
             const float* __restrict__ fc1_w, const float* __restrict__ fc2_w) {
    int idx = blockIdx.x * 256 + threadIdx.x;
    if (idx >= WTOT / 4) return;
    int i4 = idx * 4;
    const float* src;
    int off;
    if (i4 < OFF_PROJ)      { src = qkv_w;  off = i4; }
    else if (i4 < OFF_FC1)  { src = proj_w; off = i4 - OFF_PROJ; }
    else if (i4 < OFF_FC2)  { src = fc1_w;  off = i4 - OFF_FC1; }
    else                    { src = fc2_w;  off = i4 - OFF_FC2; }
    float4 v = *reinterpret_cast<const float4*>(src + off);
    __nv_bfloat16 h[4], l[4];
    splitf(v.x, h[0], l[0]); splitf(v.y, h[1], l[1]);
    splitf(v.z, h[2], l[2]); splitf(v.w, h[3], l[3]);
    *reinterpret_cast<uint2*>(g_Wh + i4) = *reinterpret_cast<uint2*>(h);
    *reinterpret_cast<uint2*>(g_Wl + i4) = *reinterpret_cast<uint2*>(l);
}

// ---------------- LN1 + window partition ----------------
__global__ void __launch_bounds__(256)
ln1_kernel(const float* __restrict__ x, const float* __restrict__ g,
           const float* __restrict__ b) {
    extern __shared__ float smf[];
    float* tile = smf;
    float* smu  = smf + 64 * 193;
    float* srs  = smu + 64;

    int win = blockIdx.x;
    int bi = win >> 6, wy = (win >> 3) & 7, wx = win & 7;
    const float* xb = x + (size_t)bi * CDIM * HW;

    for (int i = threadIdx.x; i < NTOK * CDIM; i += blockDim.x) {
        int c = i >> 6, n = i & 63;
        int iy = n >> 3, ix = n & 7;
        int hw = ((wy << 3) + iy) * IMGW + (wx << 3) + ix;
        tile[n * 193 + c] = xb[(size_t)c * HW + hw];
    }
    __syncthreads();
    if (threadIdx.x < NTOK) {
        int n = threadIdx.x;
        float s = 0.f, ss = 0.f;
        #pragma unroll 4
        for (int c = 0; c < CDIM; c++) {
            float v = tile[n * 193 + c];
            s += v; ss += v * v;
        }
        float mu = s * (1.0f / CDIM);
        float var = ss * (1.0f / CDIM) - mu * mu;
        smu[n] = mu;
        srs[n] = rsqrtf(fmaxf(var, 0.f) + 1e-5f);
    }
    __syncthreads();
    size_t ob = (size_t)win * NTOK * CDIM;
    for (int i = threadIdx.x; i < NTOK * CDIM; i += blockDim.x) {
        int n = i / CDIM, c = i - n * CDIM;
        float v = (tile[n * 193 + c] - smu[n]) * srs[n] * g[c] + b[c];
        g_S[ob + i] = v;
        __nv_bfloat16 hh, ll;
        splitf(v, hh, ll);
        g_Sh[ob + i] = hh;
        g_Sl[ob + i] = ll;
    }
}

// ---------------- LN2 normalize -> planes ----------------
__global__ void __launch_bounds__(256)
ln2_norm_kernel(const float* __restrict__ g, const float* __restrict__ b) {
    int r = blockIdx.x * 8 + (threadIdx.x >> 5);
    int lane = threadIdx.x & 31;
    const float* row = g_X2 + (size_t)r * CDIM;
    float2 v[3];
    float s = 0.f, ss = 0.f;
    #pragma unroll
    for (int i = 0; i < 3; i++) {
        v[i] = *reinterpret_cast<const float2*>(row + i * 64 + lane * 2);
        s += v[i].x + v[i].y;
        ss += v[i].x * v[i].x + v[i].y * v[i].y;
    }
    #pragma unroll
    for (int o = 16; o > 0; o >>= 1) {
        s  += __shfl_xor_sync(0xffffffffu, s,  o);
        ss += __shfl_xor_sync(0xffffffffu, ss, o);
    }
    float mu = s * (1.0f / CDIM);
    float var = ss * (1.0f / CDIM) - mu * mu;
    float rs = rsqrtf(fmaxf(var, 0.f) + 1e-5f);
    #pragma unroll
    for (int i = 0; i < 3; i++) {
        int c = i * 64 + lane * 2;
        float2 gg = *reinterpret_cast<const float2*>(g + c);
        float2 bb = *reinterpret_cast<const float2*>(b + c);
        float vx = (v[i].x - mu) * rs * gg.x + bb.x;
        float vy = (v[i].y - mu) * rs * gg.y + bb.y;
        unsigned hp, lp;
        split_pair(vx, vy, hp, lp);
        *reinterpret_cast<unsigned*>(g_Nh + (size_t)r * CDIM + c) = hp;
        *reinterpret_cast<unsigned*>(g_Nl + (size_t)r * CDIM + c) = lp;
    }
}

// ---------------- attention: HMMA logits/AV + redux topk ----------------
#define A_QH  0        // 64*40*2 = 5120   (later aliased by PH/PL)
#define A_QL  5120
#define A_KH  10240
#define A_KL  15360
#define A_PH  0        // 64*72*2 = 9216
#define A_PL  9216
#define A_VTH 20480    // 32*72*2 = 4608
#define A_VTL 25088
#define A_SA  29696    // 64*65*4 = 16640 fp32  (aliased by s_v staging 64*37*4)
#define A_SV  29696
#define A_ST  46336    // 225*4
#define ATTN_SMEM 47296

__global__ void __launch_bounds__(256)
attn_kernel(const float* __restrict__ rpb, const float* __restrict__ temp) {
    extern __shared__ char smc[];
    uint32_t sb = smem_to_u32(smc);
    __nv_bfloat16* qh = reinterpret_cast<__nv_bfloat16*>(smc + A_QH);
    __nv_bfloat16* ql = reinterpret_cast<__nv_bfloat16*>(smc + A_QL);
    __nv_bfloat16* kh = reinterpret_cast<__nv_bfloat16*>(smc + A_KH);
    __nv_bfloat16* kl = reinterpret_cast<__nv_bfloat16*>(smc + A_KL);
    __nv_bfloat16* ph = reinterpret_cast<__nv_bfloat16*>(smc + A_PH);
    __nv_bfloat16* pl = reinterpret_cast<__nv_bfloat16*>(smc + A_PL);
    float* s_a = reinterpret_cast<float*>(smc + A_SA);
    float* s_v = reinterpret_cast<float*>(smc + A_SV);
    float* s_t = reinterpret_cast<float*>(smc + A_ST);

    int blk = blockIdx.x;
    int win = blk / HEADS;
    int h = blk - win * HEADS;
    int tid = threadIdx.x, lane = tid & 31, w = tid >> 5;
    size_t base = (size_t)win * NTOK;
    float tmp = temp[h];

    for (int i = tid; i < 225; i += 256) s_t[i] = rpb[i * HEADS + h];

    uint32_t aRow = lane & 15;
    uint32_t aK   = (lane >> 4) * 8;
    uint32_t bN   = ((lane >> 4) & 1) * 8 + (lane & 7);
    uint32_t bK   = ((lane >> 3) & 1) * 8;

    // ---- phase 1: load + l2norm q,k -> planes; v -> fp32 staging ----
    for (int n = w; n < NTOK; n += 8) {
        const float* qp = g_QKV + (base + n) * CH3 + h * HD;
        float qv = qp[lane], kv = qp[192 + lane], vv = qp[384 + lane];
        float qs = qv * qv, ks = kv * kv;
        #pragma unroll
        for (int o = 16; o > 0; o >>= 1) {
            qs += __shfl_xor_sync(0xffffffffu, qs, o);
            ks += __shfl_xor_sync(0xffffffffu, ks, o);
        }
        float qn = qv * (tmp / fmaxf(sqrtf(qs), 1e-12f));
        float kn = kv / fmaxf(sqrtf(ks), 1e-12f);
        __nv_bfloat16 hh, ll;
        splitf(qn, hh, ll);
        qh[n * 40 + lane] = hh; ql[n * 40 + lane] = ll;
        splitf(kn, hh, ll);
        kh[n * 40 + lane] = hh; kl[n * 40 + lane] = ll;
        s_v[n * 37 + lane] = vv;
    }
    __syncthreads();

    // ---- phase 2: transposed V planes (d-major, stride 72) ----
    {
        int d = tid >> 3, m0 = (tid & 7) * 8;
        #pragma unroll
        for (int i = 0; i < 4; i++) {
            float a = s_v[(m0 + 2 * i) * 37 + d];
            float b = s_v[(m0 + 2 * i + 1) * 37 + d];
            unsigned hp, lp;
            split_pair(a, b, hp, lp);
            reinterpret_cast<unsigned*>(smc + A_VTH)[d * 36 + m0 / 2 + i] = hp;
            reinterpret_cast<unsigned*>(smc + A_VTL)[d * 36 + m0 / 2 + i] = lp;
        }
    }
    __syncthreads();

    // ---- phase 3: logits MMA (64x64x32, bf16x3) -> s_a fp32 ----
    {
        int mw = w & 1, nw = w >> 1;
        float c[2][2][4];
        #pragma unroll
        for (int mi = 0; mi < 2; mi++)
            #pragma unroll
            for (int nj = 0; nj < 2; nj++)
                #pragma unroll
                for (int j = 0; j < 4; j++) c[mi][nj][j] = 0.f;
        #pragma unroll
        for (int kk = 0; kk < 32; kk += 16) {
            uint32_t ah[2][4], al[2][4], bh[4], bl[4];
            #pragma unroll
            for (int mi = 0; mi < 2; mi++) {
                uint32_t off = ((mw * 32 + mi * 16 + aRow) * 40 + kk + aK) * 2;
                ldm4(ah[mi], sb + A_QH + off);
                ldm4(al[mi], sb + A_QL + off);
            }
            uint32_t boff = ((nw * 16 + bN) * 40 + kk + bK) * 2;
            ldm4(bh, sb + A_KH + boff);
            ldm4(bl, sb + A_KL + boff);
            #pragma unroll
            for (int mi = 0; mi < 2; mi++)
                #pragma unroll
                for (int nj = 0; nj < 2; nj++) {
                    mma_bf16(c[mi][nj], ah[mi], bh[2 * nj], bh[2 * nj + 1]);
                    mma_bf16(c[mi][nj], ah[mi], bl[2 * nj], bl[2 * nj + 1]);
                    mma_bf16(c[mi][nj], al[mi], bh[2 * nj], bh[2 * nj + 1]);
                }
        }
        #pragma unroll
        for (int mi = 0; mi < 2; mi++)
            #pragma unroll
            for (int nj = 0; nj < 2; nj++) {
                int r = mw * 32 + mi * 16 + (lane >> 2);
                int cc = nw * 16 + nj * 8 + (lane & 3) * 2;
                s_a[r * 65 + cc]           = c[mi][nj][0];
                s_a[r * 65 + cc + 1]       = c[mi][nj][1];
                s_a[(r + 8) * 65 + cc]     = c[mi][nj][2];
                s_a[(r + 8) * 65 + cc + 1] = c[mi][nj][3];
            }
    }
    __syncthreads();

    // ---- phase 4: top-16 (redux removal, distinct-value fast path) + rpb + softmax ----
    {
        int jy0 = lane >> 3, jx0 = lane & 7;
        int jy1 = (lane + 32) >> 3, jx1 = lane & 7;
        for (int pr = w; pr < 32; pr += 8) {
            int na = pr * 2, nb = na + 1;
            float ra0 = s_a[na * 65 + lane], ra1 = s_a[na * 65 + 32 + lane];
            float rb0 = s_a[nb * 65 + lane], rb1 = s_a[nb * 65 + 32 + lane];
            unsigned oa0 = fkey(ra0), oa1 = fkey(ra1);
            unsigned ob0 = fkey(rb0), ob1 = fkey(rb1);
            unsigned ka0 = oa0, ka1 = oa1, kb0 = ob0, kb1 = ob1;
            #pragma unroll 1
            for (int it = 0; it < 15; it++) {
                unsigned ma = __reduce_max_sync(0xffffffffu, ka0 > ka1 ? ka0 : ka1);
                unsigned mb = __reduce_max_sync(0xffffffffu, kb0 > kb1 ? kb0 : kb1);
                if (ka0 == ma) ka0 = 0u; else if (ka1 == ma) ka1 = 0u;
                if (kb0 == mb) kb0 = 0u; else if (kb1 == mb) kb1 = 0u;
            }
            unsigned kta = __reduce_max_sync(0xffffffffu, ka0 > ka1 ? ka0 : ka1);
            unsigned ktb = __reduce_max_sync(0xffffffffu, kb0 > kb1 ? kb0 : kb1);

            int iya = na >> 3, ixa = na & 7;
            int iyb = nb >> 3, ixb = nb & 7;
            float ea0 = ((oa0 >= kta) ? ra0 : -100.0f) + s_t[(iya - jy0 + 7) * 15 + (ixa - jx0 + 7)];
            float ea1 = ((oa1 >= kta) ? ra1 : -100.0f) + s_t[(iya - jy1 + 7) * 15 + (ixa - jx1 + 7)];
            float eb0 = ((ob0 >= ktb) ? rb0 : -100.0f) + s_t[(iyb - jy0 + 7) * 15 + (ixb - jx0 + 7)];
            float eb1 = ((ob1 >= ktb) ? rb1 : -100.0f) + s_t[(iyb - jy1 + 7) * 15 + (ixb - jx1 + 7)];

            unsigned mka = __reduce_max_sync(0xffffffffu, fkey(fmaxf(ea0, ea1)));
            unsigned mkb = __reduce_max_sync(0xffffffffu, fkey(fmaxf(eb0, eb1)));
            float mxa = unfkey(mka), mxb = unfkey(mkb);
            float pa0 = expf(ea0 - mxa), pa1 = expf(ea1 - mxa);
            float pb0 = expf(eb0 - mxb), pb1 = expf(eb1 - mxb);
            float sa = pa0 + pa1, sbm = pb0 + pb1;
            #pragma unroll
            for (int o = 16; o > 0; o >>= 1) {
                sa  += __shfl_xor_sync(0xffffffffu, sa,  o);
                sbm += __shfl_xor_sync(0xffffffffu, sbm, o);
            }
            float ia = 1.0f / sa, ib = 1.0f / sbm;
            __nv_bfloat16 hh, ll;
            splitf(pa0 * ia, hh, ll); ph[na * 72 + lane] = hh;      pl[na * 72 + lane] = ll;
            splitf(pa1 * ia, hh, ll); ph[na * 72 + 32 + lane] = hh; pl[na * 72 + 32 + lane] = ll;
            splitf(pb0 * ib, hh, ll); ph[nb * 72 + lane] = hh;      pl[nb * 72 + lane] = ll;
            splitf(pb1 * ib, hh, ll); ph[nb * 72 + 32 + lane] = hh; pl[nb * 72 + 32 + lane] = ll;
        }
    }
    __syncthreads();

    // ---- phase 5: AV MMA (64x32x64, bf16x3) -> g_Oh/g_Ol ----
    {
        int mw = w >> 1, dw = w & 1;
        float c[2][4];
        #pragma unroll
        for (int nj = 0; nj < 2; nj++)
            #pragma unroll
            for (int j = 0; j < 4; j++) c[nj][j] = 0.f;
        #pragma unroll
        for (int kk = 0; kk < 64; kk += 16) {
            uint32_t ahh[4], all[4], bh[4], bl[4];
            uint32_t aoff = ((mw * 16 + aRow) * 72 + kk + aK) * 2;
            ldm4(ahh, sb + A_PH + aoff);
            ldm4(all, sb + A_PL + aoff);
            uint32_t boff = ((dw * 16 + bN) * 72 + kk + bK) * 2;
            ldm4(bh, sb + A_VTH + boff);
            ldm4(bl, sb + A_VTL + boff);
            #pragma unroll
            for (int nj = 0; nj < 2; nj++) {
                mma_bf16(c[nj], ahh, bh[2 * nj], bh[2 * nj + 1]);
                mma_bf16(c[nj], ahh, bl[2 * nj], bl[2 * nj + 1]);
                mma_bf16(c[nj], all, bh[2 * nj], bh[2 * nj + 1]);
            }
        }
        #pragma unroll
        for (int nj = 0; nj < 2; nj++) {
            int r0 = mw * 16 + (lane >> 2);
            int dloc = dw * 16 + nj * 8 + (lane & 3) * 2;
            size_t o0 = (base + r0) * CDIM + h * HD + dloc;
            size_t o1 = (base + r0 + 8) * CDIM + h * HD + dloc;
            unsigned hp, lp;
            split_pair(c[nj][0], c[nj][1], hp, lp);
            *reinterpret_cast<unsigned*>(g_Oh + o0) = hp;
            *reinterpret_cast<unsigned*>(g_Ol + o0) = lp;
            split_pair(c[nj][2], c[nj][3], hp, lp);
            *reinterpret_cast<unsigned*>(g_Oh + o1) = hp;
            *reinterpret_cast<unsigned*>(g_Ol + o1) = lp;
        }
    }
}

// ---------------- final transpose: g_S (token-major Y) -> NCHW out ----------------
__global__ void __launch_bounds__(256)
out_tr_kernel(float* __restrict__ out) {
    extern __shared__ float smf[];
    float* tile = smf;  // 64 x 193
    int win = blockIdx.x;
    int bi = win >> 6, wy = (win >> 3) & 7, wx = win & 7;
    const float* src = g_S + (size_t)win * NTOK * CDIM;
    for (int i = threadIdx.x; i < NTOK * CDIM; i += 256) {
        int n = i / CDIM, c = i - n * CDIM;
        tile[n * 193 + c] = src[i];
    }
    __syncthreads();
    float* ob = out + (size_t)bi * CDIM * HW;
    for (int i = threadIdx.x; i < NTOK * CDIM; i += 256) {
        int c = i >> 6, n = i & 63;
        int iy = n >> 3, ix = n & 7;
        int hw = ((wy << 3) + iy) * IMGW + (wx << 3) + ix;
        ob[(size_t)c * HW + hw] = tile[n * 193 + c];
    }
}

// ---------------- launch ----------------
extern "C" void kernel_launch(void* const* d_in, const int* in_sizes, int n_in,
                              void* d_out, int out_size) {
    const float* x      = (const float*)d_in[0];
    const float* n1g    = (const float*)d_in[1];
    const float* n1b    = (const float*)d_in[2];
    const float* qkv_w  = (const float*)d_in[3];
    const float* qkv_b  = (const float*)d_in[4];
    const float* proj_w = (const float*)d_in[5];
    const float* proj_b = (const float*)d_in[6];
    const float* rpb    = (const float*)d_in[7];
    const float* temp   = (const float*)d_in[8];
    const float* n2g    = (const float*)d_in[9];
    const float* n2b    = (const float*)d_in[10];
    const float* fc1_w  = (const float*)d_in[11];
    const float* fc1_b  = (const float*)d_in[12];
    const float* fc2_w  = (const float*)d_in[13];
    const float* fc2_b  = (const float*)d_in[14];
    float* out = (float*)d_out;

    const int LN1_SMEM  = (64 * 193 + 128) * 4;
    const int TR_SMEM   = 64 * 193 * 4;
    cudaFuncSetAttribute(ln1_kernel,    cudaFuncAttributeMaxDynamicSharedMemorySize, LN1_SMEM);
    cudaFuncSetAttribute(attn_kernel,   cudaFuncAttributeMaxDynamicSharedMemorySize, ATTN_SMEM);
    cudaFuncSetAttribute(out_tr_kernel, cudaFuncAttributeMaxDynamicSharedMemorySize, TR_SMEM);
    cudaFuncSetAttribute(gemm_mma<0, 192>, cudaFuncAttributeMaxDynamicSharedMemorySize, GSMEM);
    cudaFuncSetAttribute(gemm_mma<1, 192>, cudaFuncAttributeMaxDynamicSharedMemorySize, GSMEM);
    cudaFuncSetAttribute(gemm_mma<2, 192>, cudaFuncAttributeMaxDynamicSharedMemorySize, GSMEM);
    cudaFuncSetAttribute(gemm_mma<3, 768>, cudaFuncAttributeMaxDynamicSharedMemorySize, GSMEM);

    wconv_kernel<<<(WTOT / 4 + 255) / 256, 256>>>(qkv_w, proj_w, fc1_w, fc2_w);
    ln1_kernel<<<NWIN, 256, LN1_SMEM>>>(x, n1g, n1b);
    gemm_mma<0, 192><<<dim3(ROWS / 128, CH3 / 96), GTHREADS, GSMEM>>>(qkv_b);
    attn_kernel<<<NWIN * HEADS, 256, ATTN_SMEM>>>(rpb, temp);
    gemm_mma<1, 192><<<dim3(ROWS / 128, CDIM / 96), GTHREADS, GSMEM>>>(proj_b);
    ln2_norm_kernel<<<ROWS / 8, 256>>>(n2g, n2b);
    gemm_mma<2, 192><<<dim3(ROWS / 128, FF / 96), GTHREADS, GSMEM>>>(fc1_b);
    gemm_mma<3, 768><<<dim3(ROWS / 128, CDIM / 96), GTHREADS, GSMEM>>>(fc2_b);
    out_tr_kernel<<<NWIN, 256, TR_SMEM>>>(out);
}

// round 17
// speedup vs baseline: 1.6122x; 1.4655x over previous
#include <cuda_runtime.h>
#include <cuda_bf16.h>
#include <math.h>
#include <stdint.h>

// ---------------- problem constants ----------------
#define BATCH   8
#define CDIM    192
#define HEADS   6
#define HD      32
#define NTOK    64
#define NWIN    512
#define ROWS    32768
#define CH3     576
#define FF      768
#define HW      4096
#define IMGW    64

// weight plane offsets (elements)
#define OFF_QKV  0
#define OFF_PROJ 110592
#define OFF_FC1  147456
#define OFF_FC2  294912
#define WTOT     442368

// ---------------- scratch ----------------
__device__ float g_S  [ROWS * (size_t)CDIM];   // LN1 fp32 (shortcut); reused as final token-major Y
__device__ float g_QKV[ROWS * (size_t)CH3];
__device__ float g_X2 [ROWS * (size_t)CDIM];

__device__ __nv_bfloat16 g_Sh[ROWS * (size_t)CDIM], g_Sl[ROWS * (size_t)CDIM];  // LN1 planes (qkv: 3-pass)
__device__ __nv_bfloat16 g_Oh[ROWS * (size_t)CDIM];   // attn out, single bf16 (proj: 1-pass)
__device__ __nv_bfloat16 g_Nh[ROWS * (size_t)CDIM];   // LN2 out,  single bf16 (fc1: 1-pass)
__device__ __nv_bfloat16 g_Hh[ROWS * (size_t)FF];     // gelu out, single bf16 (fc2: 1-pass)
__device__ __nv_bfloat16 g_Wh[WTOT], g_Wl[WTOT];

// ---------------- helpers ----------------
__device__ __forceinline__ uint32_t smem_to_u32(const void* p) {
    uint32_t a;
    asm("{ .reg .u64 t; cvta.to.shared.u64 t, %1; cvt.u32.u64 %0, t; }" : "=r"(a) : "l"(p));
    return a;
}
__device__ __forceinline__ void ldm4(uint32_t* r, uint32_t addr) {
    asm volatile("ldmatrix.sync.aligned.m8n8.x4.shared.b16 {%0,%1,%2,%3}, [%4];"
                 : "=r"(r[0]), "=r"(r[1]), "=r"(r[2]), "=r"(r[3]) : "r"(addr));
}
__device__ __forceinline__ void mma_bf16(float* c, const uint32_t* a, uint32_t b0, uint32_t b1) {
    asm volatile("mma.sync.aligned.m16n8k16.row.col.f32.bf16.bf16.f32 "
                 "{%0,%1,%2,%3}, {%4,%5,%6,%7}, {%8,%9}, {%0,%1,%2,%3};"
                 : "+f"(c[0]), "+f"(c[1]), "+f"(c[2]), "+f"(c[3])
                 : "r"(a[0]), "r"(a[1]), "r"(a[2]), "r"(a[3]), "r"(b0), "r"(b1));
}
__device__ __forceinline__ void splitf(float v, __nv_bfloat16& h, __nv_bfloat16& l) {
    h = __float2bfloat16(v);
    l = __float2bfloat16(v - __bfloat162float(h));
}
__device__ __forceinline__ void split_pair(float x, float y, unsigned& h, unsigned& l) {
    __nv_bfloat16 hx, lx, hy, ly;
    splitf(x, hx, lx);
    splitf(y, hy, ly);
    __nv_bfloat162 hh = __halves2bfloat162(hx, hy);
    __nv_bfloat162 ll = __halves2bfloat162(lx, ly);
    h = *reinterpret_cast<unsigned*>(&hh);
    l = *reinterpret_cast<unsigned*>(&ll);
}
__device__ __forceinline__ unsigned pack_bf16x2(float x, float y) {
    __nv_bfloat162 p = __halves2bfloat162(__float2bfloat16(x), __float2bfloat16(y));
    return *reinterpret_cast<unsigned*>(&p);
}
// monotonic float->u32 key (order-preserving)
__device__ __forceinline__ unsigned fkey(float v) {
    unsigned u = __float_as_uint(v);
    return (u & 0x80000000u) ? ~u : (u | 0x80000000u);
}
__device__ __forceinline__ float unfkey(unsigned k) {
    return __uint_as_float((k & 0x80000000u) ? (k & 0x7fffffffu) : ~k);
}
#define CP16(sdst, gsrc) \
    asm volatile("cp.async.ca.shared.global [%0], [%1], 16;" :: "r"(sdst), "l"(gsrc) : "memory")
#define CP_COMMIT() asm volatile("cp.async.commit_group;" ::: "memory")

// ---------------- bf16 HMMA GEMM, 128x64 CTA tile (R10 shape), NS=3 or 1 passes ----------------
// MODE 0 (NS=3): A=g_Sh/l, B=W[qkv]  -> g_QKV fp32                 (K=192, N=576)
// MODE 1 (NS=1): A=g_Oh,   B=W[proj] -> g_X2 = g_S + .             (K=192, N=192)
// MODE 2 (NS=1): A=g_Nh,   B=W[fc1]  -> g_Hh = bf16(gelu(.))       (K=192, N=768)
// MODE 3 (NS=1): A=g_Hh,   B=W[fc2]  -> g_S (token-major) = g_X2+. (K=768, N=192)
template<int MODE, int K, int NS>
__global__ void __launch_bounds__(256)
gemm_mma(const float* __restrict__ bias) {
    extern __shared__ char sm[];
    uint32_t sb = smem_to_u32(sm);

    constexpr int AL_O = 10240;                        // NS==3 only
    constexpr int BH_O = (NS == 3) ? 20480 : 10240;
    constexpr int BL_O = 25600;                        // NS==3 only
    constexpr int STGc = (NS == 3) ? 30720 : 15360;

    const __nv_bfloat16* Ah_g = (MODE == 0) ? g_Sh : (MODE == 1) ? g_Oh : (MODE == 2) ? g_Nh : g_Hh;
    const __nv_bfloat16* Al_g = g_Sl;                  // used only when NS==3 (MODE 0)
    constexpr int WOFF = (MODE == 0) ? OFF_QKV : (MODE == 1) ? OFF_PROJ : (MODE == 2) ? OFF_FC1 : OFF_FC2;
    const __nv_bfloat16* Bh_g = g_Wh + WOFF;
    const __nv_bfloat16* Bl_g = g_Wl + WOFF;

    int tid = threadIdx.x;
    int lane = tid & 31, w = tid >> 5;
    int wm = (w >> 1) * 32, wn = (w & 1) * 32;
    int rbase = blockIdx.x * 128, cbase = blockIdx.y * 64;

    uint32_t aRow = (lane & 7) + ((lane >> 3) & 1) * 8;
    uint32_t aK   = (lane >> 4) * 8;
    uint32_t bN   = ((lane >> 4) & 1) * 8 + (lane & 7);
    uint32_t bK   = ((lane >> 3) & 1) * 8;

    float acc[2][4][4];
    #pragma unroll
    for (int mi = 0; mi < 2; mi++)
        #pragma unroll
        for (int ni = 0; ni < 4; ni++)
            #pragma unroll
            for (int j = 0; j < 4; j++) acc[mi][ni][j] = 0.f;

    auto copy_stage = [&](int st, int kt) {
        uint32_t base = sb + st * STGc;
        #pragma unroll
        for (int i = 0; i < 2; i++) {
            int g = i * 256 + tid;
            int r = g >> 2, s2 = g & 3;
            size_t go = (size_t)(rbase + r) * K + kt + s2 * 8;
            uint32_t so = (uint32_t)(r * 40 + s2 * 8) * 2;
            CP16(base + so, Ah_g + go);
            if (NS == 3) CP16(base + AL_O + so, Al_g + go);
        }
        {
            int r = tid >> 2, s2 = tid & 3;
            size_t go = (size_t)(cbase + r) * K + kt + s2 * 8;
            uint32_t so = (uint32_t)(r * 40 + s2 * 8) * 2;
            CP16(base + BH_O + so, Bh_g + go);
            if (NS == 3) CP16(base + BL_O + so, Bl_g + go);
        }
        CP_COMMIT();
    };

    constexpr int NC = K / 32;
    copy_stage(0, 0);

    for (int c = 0; c < NC; c++) {
        if (c + 1 < NC) {
            copy_stage((c + 1) & 1, (c + 1) * 32);
            asm volatile("cp.async.wait_group 1;" ::: "memory");
        } else {
            asm volatile("cp.async.wait_group 0;" ::: "memory");
        }
        __syncthreads();

        uint32_t stb = sb + (c & 1) * STGc;
        #pragma unroll
        for (int kk = 0; kk < 32; kk += 16) {
            uint32_t ah[2][4], al[2][4], bh[2][4], bl[2][4];
            #pragma unroll
            for (int p = 0; p < 2; p++) {
                uint32_t off = ((wn + p * 16 + bN) * 40 + kk + bK) * 2;
                ldm4(bh[p], stb + BH_O + off);
                if (NS == 3) ldm4(bl[p], stb + BL_O + off);
            }
            #pragma unroll
            for (int mi = 0; mi < 2; mi++) {
                uint32_t off = ((wm + mi * 16 + aRow) * 40 + kk + aK) * 2;
                ldm4(ah[mi], stb + off);
                if (NS == 3) ldm4(al[mi], stb + AL_O + off);
            }
            #pragma unroll
            for (int mi = 0; mi < 2; mi++)
                #pragma unroll
                for (int ni = 0; ni < 4; ni++) {
                    int p = ni >> 1, o = (ni & 1) * 2;
                    mma_bf16(acc[mi][ni], ah[mi], bh[p][o], bh[p][o + 1]);
                    if (NS == 3) {
                        mma_bf16(acc[mi][ni], ah[mi], bl[p][o], bl[p][o + 1]);
                        mma_bf16(acc[mi][ni], al[mi], bh[p][o], bh[p][o + 1]);
                    }
                }
        }
        __syncthreads();
    }

    // ---- epilogue: frags -> smem fp32 tile (128x65) -> coalesced global ----
    float* st = reinterpret_cast<float*>(sm);
    #pragma unroll
    for (int mi = 0; mi < 2; mi++)
        #pragma unroll
        for (int ni = 0; ni < 4; ni++) {
            int row = wm + mi * 16 + (lane >> 2);
            int col = wn + ni * 8 + (lane & 3) * 2;
            st[row * 65 + col]           = acc[mi][ni][0];
            st[row * 65 + col + 1]       = acc[mi][ni][1];
            st[(row + 8) * 65 + col]     = acc[mi][ni][2];
            st[(row + 8) * 65 + col + 1] = acc[mi][ni][3];
        }
    __syncthreads();

    for (int i = tid; i < 128 * 64; i += 256) {
        int row = i >> 6, j = i & 63;
        int r = rbase + row, cc = cbase + j;
        float v = st[row * 65 + j] + bias[cc];
        if (MODE == 0) {
            g_QKV[(size_t)r * CH3 + cc] = v;
        } else if (MODE == 1) {
            g_X2[(size_t)r * CDIM + cc] = g_S[(size_t)r * CDIM + cc] + v;
        } else if (MODE == 2) {
            float a = 0.5f * v * (1.0f + erff(v * 0.70710678118654752f));
            g_Hh[(size_t)r * FF + cc] = __float2bfloat16(a);
        } else {
            g_S[(size_t)r * CDIM + cc] = g_X2[(size_t)r * CDIM + cc] + v;
        }
    }
}

#define GSMEM3 61440
#define GSMEM1 33280   // max(2*15360, 128*65*4 epilogue)

// ---------------- weight conversion ----------------
__global__ void __launch_bounds__(256)
wconv_kernel(const float* __restrict__ qkv_w, const float* __restrict__ proj_w,
             const float* __restrict__ fc1_w, const float* __restrict__ fc2_w) {
    int idx = blockIdx.x * 256 + threadIdx.x;
    if (idx >= WTOT / 4) return;
    int i4 = idx * 4;
    const float* src;
    int off;
    if (i4 < OFF_PROJ)      { src = qkv_w;  off = i4; }
    else if (i4 < OFF_FC1)  { src = proj_w; off = i4 - OFF_PROJ; }
    else if (i4 < OFF_FC2)  { src = fc1_w;  off = i4 - OFF_FC1; }
    else                    { src = fc2_w;  off = i4 - OFF_FC2; }
    float4 v = *reinterpret_cast<const float4*>(src + off);
    __nv_bfloat16 h[4], l[4];
    splitf(v.x, h[0], l[0]); splitf(v.y, h[1], l[1]);
    splitf(v.z, h[2], l[2]); splitf(v.w, h[3], l[3]);
    *reinterpret_cast<uint2*>(g_Wh + i4) = *reinterpret_cast<uint2*>(h);
    *reinterpret_cast<uint2*>(g_Wl + i4) = *reinterpret_cast<uint2*>(l);
}

// ---------------- LN1 + window partition ----------------
__global__ void __launch_bounds__(256)
ln1_kernel(const float* __restrict__ x, const float* __restrict__ g,
           const float* __restrict__ b) {
    extern __shared__ float smf[];
    float* tile = smf;
    float* smu  = smf + 64 * 193;
    float* srs  = smu + 64;

    int win = blockIdx.x;
    int bi = win >> 6, wy = (win >> 3) & 7, wx = win & 7;
    const float* xb = x + (size_t)bi * CDIM * HW;

    for (int i = threadIdx.x; i < NTOK * CDIM; i += blockDim.x) {
        int c = i >> 6, n = i & 63;
        int iy = n >> 3, ix = n & 7;
        int hw = ((wy << 3) + iy) * IMGW + (wx << 3) + ix;
        tile[n * 193 + c] = xb[(size_t)c * HW + hw];
    }
    __syncthreads();
    if (threadIdx.x < NTOK) {
        int n = threadIdx.x;
        float s = 0.f, ss = 0.f;
        #pragma unroll 4
        for (int c = 0; c < CDIM; c++) {
            float v = tile[n * 193 + c];
            s += v; ss += v * v;
        }
        float mu = s * (1.0f / CDIM);
        float var = ss * (1.0f / CDIM) - mu * mu;
        smu[n] = mu;
        srs[n] = rsqrtf(fmaxf(var, 0.f) + 1e-5f);
    }
    __syncthreads();
    size_t ob = (size_t)win * NTOK * CDIM;
    for (int i = threadIdx.x; i < NTOK * CDIM; i += blockDim.x) {
        int n = i / CDIM, c = i - n * CDIM;
        float v = (tile[n * 193 + c] - smu[n]) * srs[n] * g[c] + b[c];
        g_S[ob + i] = v;
        __nv_bfloat16 hh, ll;
        splitf(v, hh, ll);
        g_Sh[ob + i] = hh;
        g_Sl[ob + i] = ll;
    }
}

// ---------------- LN2 normalize -> single bf16 plane ----------------
__global__ void __launch_bounds__(256)
ln2_norm_kernel(const float* __restrict__ g, const float* __restrict__ b) {
    int r = blockIdx.x * 8 + (threadIdx.x >> 5);
    int lane = threadIdx.x & 31;
    const float* row = g_X2 + (size_t)r * CDIM;
    float2 v[3];
    float s = 0.f, ss = 0.f;
    #pragma unroll
    for (int i = 0; i < 3; i++) {
        v[i] = *reinterpret_cast<const float2*>(row + i * 64 + lane * 2);
        s += v[i].x + v[i].y;
        ss += v[i].x * v[i].x + v[i].y * v[i].y;
    }
    #pragma unroll
    for (int o = 16; o > 0; o >>= 1) {
        s  += __shfl_xor_sync(0xffffffffu, s,  o);
        ss += __shfl_xor_sync(0xffffffffu, ss, o);
    }
    float mu = s * (1.0f / CDIM);
    float var = ss * (1.0f / CDIM) - mu * mu;
    float rs = rsqrtf(fmaxf(var, 0.f) + 1e-5f);
    #pragma unroll
    for (int i = 0; i < 3; i++) {
        int c = i * 64 + lane * 2;
        float2 gg = *reinterpret_cast<const float2*>(g + c);
        float2 bb = *reinterpret_cast<const float2*>(b + c);
        float vx = (v[i].x - mu) * rs * gg.x + bb.x;
        float vy = (v[i].y - mu) * rs * gg.y + bb.y;
        *reinterpret_cast<unsigned*>(g_Nh + (size_t)r * CDIM + c) = pack_bf16x2(vx, vy);
    }
}

// ---------------- attention: HMMA logits/AV + redux topk ----------------
#define A_QH  0        // 64*40*2 = 5120   (later aliased by PH/PL)
#define A_QL  5120
#define A_KH  10240
#define A_KL  15360
#define A_PH  0        // 64*72*2 = 9216
#define A_PL  9216
#define A_VTH 20480    // 32*72*2 = 4608
#define A_VTL 25088
#define A_SA  29696    // 64*65*4 = 16640 fp32  (aliased by s_v staging 64*37*4)
#define A_SV  29696
#define A_ST  46336    // 225*4
#define ATTN_SMEM 47296

__global__ void __launch_bounds__(256)
attn_kernel(const float* __restrict__ rpb, const float* __restrict__ temp) {
    extern __shared__ char smc[];
    uint32_t sb = smem_to_u32(smc);
    __nv_bfloat16* qh = reinterpret_cast<__nv_bfloat16*>(smc + A_QH);
    __nv_bfloat16* ql = reinterpret_cast<__nv_bfloat16*>(smc + A_QL);
    __nv_bfloat16* kh = reinterpret_cast<__nv_bfloat16*>(smc + A_KH);
    __nv_bfloat16* kl = reinterpret_cast<__nv_bfloat16*>(smc + A_KL);
    __nv_bfloat16* ph = reinterpret_cast<__nv_bfloat16*>(smc + A_PH);
    __nv_bfloat16* pl = reinterpret_cast<__nv_bfloat16*>(smc + A_PL);
    float* s_a = reinterpret_cast<float*>(smc + A_SA);
    float* s_v = reinterpret_cast<float*>(smc + A_SV);
    float* s_t = reinterpret_cast<float*>(smc + A_ST);

    int blk = blockIdx.x;
    int win = blk / HEADS;
    int h = blk - win * HEADS;
    int tid = threadIdx.x, lane = tid & 31, w = tid >> 5;
    size_t base = (size_t)win * NTOK;
    float tmp = temp[h];

    for (int i = tid; i < 225; i += 256) s_t[i] = rpb[i * HEADS + h];

    uint32_t aRow = lane & 15;
    uint32_t aK   = (lane >> 4) * 8;
    uint32_t bN   = ((lane >> 4) & 1) * 8 + (lane & 7);
    uint32_t bK   = ((lane >> 3) & 1) * 8;

    // ---- phase 1: load + l2norm q,k -> planes; v -> fp32 staging ----
    for (int n = w; n < NTOK; n += 8) {
        const float* qp = g_QKV + (base + n) * CH3 + h * HD;
        float qv = qp[lane], kv = qp[192 + lane], vv = qp[384 + lane];
        float qs = qv * qv, ks = kv * kv;
        #pragma unroll
        for (int o = 16; o > 0; o >>= 1) {
            qs += __shfl_xor_sync(0xffffffffu, qs, o);
            ks += __shfl_xor_sync(0xffffffffu, ks, o);
        }
        float qn = qv * (tmp / fmaxf(sqrtf(qs), 1e-12f));
        float kn = kv / fmaxf(sqrtf(ks), 1e-12f);
        __nv_bfloat16 hh, ll;
        splitf(qn, hh, ll);
        qh[n * 40 + lane] = hh; ql[n * 40 + lane] = ll;
        splitf(kn, hh, ll);
        kh[n * 40 + lane] = hh; kl[n * 40 + lane] = ll;
        s_v[n * 37 + lane] = vv;
    }
    __syncthreads();

    // ---- phase 2: transposed V planes (d-major, stride 72) ----
    {
        int d = tid >> 3, m0 = (tid & 7) * 8;
        #pragma unroll
        for (int i = 0; i < 4; i++) {
            float a = s_v[(m0 + 2 * i) * 37 + d];
            float b = s_v[(m0 + 2 * i + 1) * 37 + d];
            unsigned hp, lp;
            split_pair(a, b, hp, lp);
            reinterpret_cast<unsigned*>(smc + A_VTH)[d * 36 + m0 / 2 + i] = hp;
            reinterpret_cast<unsigned*>(smc + A_VTL)[d * 36 + m0 / 2 + i] = lp;
        }
    }
    __syncthreads();

    // ---- phase 3: logits MMA (64x64x32, bf16x3) -> s_a fp32 ----
    {
        int mw = w & 1, nw = w >> 1;
        float c[2][2][4];
        #pragma unroll
        for (int mi = 0; mi < 2; mi++)
            #pragma unroll
            for (int nj = 0; nj < 2; nj++)
                #pragma unroll
                for (int j = 0; j < 4; j++) c[mi][nj][j] = 0.f;
        #pragma unroll
        for (int kk = 0; kk < 32; kk += 16) {
            uint32_t ah[2][4], al[2][4], bh[4], bl[4];
            #pragma unroll
            for (int mi = 0; mi < 2; mi++) {
                uint32_t off = ((mw * 32 + mi * 16 + aRow) * 40 + kk + aK) * 2;
                ldm4(ah[mi], sb + A_QH + off);
                ldm4(al[mi], sb + A_QL + off);
            }
            uint32_t boff = ((nw * 16 + bN) * 40 + kk + bK) * 2;
            ldm4(bh, sb + A_KH + boff);
            ldm4(bl, sb + A_KL + boff);
            #pragma unroll
            for (int mi = 0; mi < 2; mi++)
                #pragma unroll
                for (int nj = 0; nj < 2; nj++) {
                    mma_bf16(c[mi][nj], ah[mi], bh[2 * nj], bh[2 * nj + 1]);
                    mma_bf16(c[mi][nj], ah[mi], bl[2 * nj], bl[2 * nj + 1]);
                    mma_bf16(c[mi][nj], al[mi], bh[2 * nj], bh[2 * nj + 1]);
                }
        }
        #pragma unroll
        for (int mi = 0; mi < 2; mi++)
            #pragma unroll
            for (int nj = 0; nj < 2; nj++) {
                int r = mw * 32 + mi * 16 + (lane >> 2);
                int cc = nw * 16 + nj * 8 + (lane & 3) * 2;
                s_a[r * 65 + cc]           = c[mi][nj][0];
                s_a[r * 65 + cc + 1]       = c[mi][nj][1];
                s_a[(r + 8) * 65 + cc]     = c[mi][nj][2];
                s_a[(r + 8) * 65 + cc + 1] = c[mi][nj][3];
            }
    }
    __syncthreads();

    // ---- phase 4: top-16 (redux removal, distinct-value fast path) + rpb + softmax ----
    {
        int jy0 = lane >> 3, jx0 = lane & 7;
        int jy1 = (lane + 32) >> 3, jx1 = lane & 7;
        for (int pr = w; pr < 32; pr += 8) {
            int na = pr * 2, nb = na + 1;
            float ra0 = s_a[na * 65 + lane], ra1 = s_a[na * 65 + 32 + lane];
            float rb0 = s_a[nb * 65 + lane], rb1 = s_a[nb * 65 + 32 + lane];
            unsigned oa0 = fkey(ra0), oa1 = fkey(ra1);
            unsigned ob0 = fkey(rb0), ob1 = fkey(rb1);
            unsigned ka0 = oa0, ka1 = oa1, kb0 = ob0, kb1 = ob1;
            #pragma unroll 1
            for (int it = 0; it < 15; it++) {
                unsigned ma = __reduce_max_sync(0xffffffffu, ka0 > ka1 ? ka0 : ka1);
                unsigned mb = __reduce_max_sync(0xffffffffu, kb0 > kb1 ? kb0 : kb1);
                if (ka0 == ma) ka0 = 0u; else if (ka1 == ma) ka1 = 0u;
                if (kb0 == mb) kb0 = 0u; else if (kb1 == mb) kb1 = 0u;
            }
            unsigned kta = __reduce_max_sync(0xffffffffu, ka0 > ka1 ? ka0 : ka1);
            unsigned ktb = __reduce_max_sync(0xffffffffu, kb0 > kb1 ? kb0 : kb1);

            int iya = na >> 3, ixa = na & 7;
            int iyb = nb >> 3, ixb = nb & 7;
            float ea0 = ((oa0 >= kta) ? ra0 : -100.0f) + s_t[(iya - jy0 + 7) * 15 + (ixa - jx0 + 7)];
            float ea1 = ((oa1 >= kta) ? ra1 : -100.0f) + s_t[(iya - jy1 + 7) * 15 + (ixa - jx1 + 7)];
            float eb0 = ((ob0 >= ktb) ? rb0 : -100.0f) + s_t[(iyb - jy0 + 7) * 15 + (ixb - jx0 + 7)];
            float eb1 = ((ob1 >= ktb) ? rb1 : -100.0f) + s_t[(iyb - jy1 + 7) * 15 + (ixb - jx1 + 7)];

            unsigned mka = __reduce_max_sync(0xffffffffu, fkey(fmaxf(ea0, ea1)));
            unsigned mkb = __reduce_max_sync(0xffffffffu, fkey(fmaxf(eb0, eb1)));
            float mxa = unfkey(mka), mxb = unfkey(mkb);
            float pa0 = expf(ea0 - mxa), pa1 = expf(ea1 - mxa);
            float pb0 = expf(eb0 - mxb), pb1 = expf(eb1 - mxb);
            float sa = pa0 + pa1, sbm = pb0 + pb1;
            #pragma unroll
            for (int o = 16; o > 0; o >>= 1) {
                sa  += __shfl_xor_sync(0xffffffffu, sa,  o);
                sbm += __shfl_xor_sync(0xffffffffu, sbm, o);
            }
            float ia = 1.0f / sa, ib = 1.0f / sbm;
            __nv_bfloat16 hh, ll;
            splitf(pa0 * ia, hh, ll); ph[na * 72 + lane] = hh;      pl[na * 72 + lane] = ll;
            splitf(pa1 * ia, hh, ll); ph[na * 72 + 32 + lane] = hh; pl[na * 72 + 32 + lane] = ll;
            splitf(pb0 * ib, hh, ll); ph[nb * 72 + lane] = hh;      pl[nb * 72 + lane] = ll;
            splitf(pb1 * ib, hh, ll); ph[nb * 72 + 32 + lane] = hh; pl[nb * 72 + 32 + lane] = ll;
        }
    }
    __syncthreads();

    // ---- phase 5: AV MMA (64x32x64, bf16x3) -> g_Oh (single bf16; proj is 1-pass) ----
    {
        int mw = w >> 1, dw = w & 1;
        float c[2][4];
        #pragma unroll
        for (int nj = 0; nj < 2; nj++)
            #pragma unroll
            for (int j = 0; j < 4; j++) c[nj][j] = 0.f;
        #pragma unroll
        for (int kk = 0; kk < 64; kk += 16) {
            uint32_t ahh[4], all[4], bh[4], bl[4];
            uint32_t aoff = ((mw * 16 + aRow) * 72 + kk + aK) * 2;
            ldm4(ahh, sb + A_PH + aoff);
            ldm4(all, sb + A_PL + aoff);
            uint32_t boff = ((dw * 16 + bN) * 72 + kk + bK) * 2;
            ldm4(bh, sb + A_VTH + boff);
            ldm4(bl, sb + A_VTL + boff);
            #pragma unroll
            for (int nj = 0; nj < 2; nj++) {
                mma_bf16(c[nj], ahh, bh[2 * nj], bh[2 * nj + 1]);
                mma_bf16(c[nj], ahh, bl[2 * nj], bl[2 * nj + 1]);
                mma_bf16(c[nj], all, bh[2 * nj], bh[2 * nj + 1]);
            }
        }
        #pragma unroll
        for (int nj = 0; nj < 2; nj++) {
            int r0 = mw * 16 + (lane >> 2);
            int dloc = dw * 16 + nj * 8 + (lane & 3) * 2;
            size_t o0 = (base + r0) * CDIM + h * HD + dloc;
            size_t o1 = (base + r0 + 8) * CDIM + h * HD + dloc;
            *reinterpret_cast<unsigned*>(g_Oh + o0) = pack_bf16x2(c[nj][0], c[nj][1]);
            *reinterpret_cast<unsigned*>(g_Oh + o1) = pack_bf16x2(c[nj][2], c[nj][3]);
        }
    }
}

// ---------------- final transpose: g_S (token-major Y) -> NCHW out ----------------
__global__ void __launch_bounds__(256)
out_tr_kernel(float* __restrict__ out) {
    extern __shared__ float smf[];
    float* tile = smf;  // 64 x 193
    int win = blockIdx.x;
    int bi = win >> 6, wy = (win >> 3) & 7, wx = win & 7;
    const float* src = g_S + (size_t)win * NTOK * CDIM;
    for (int i = threadIdx.x; i < NTOK * CDIM; i += 256) {
        int n = i / CDIM, c = i - n * CDIM;
        tile[n * 193 + c] = src[i];
    }
    __syncthreads();
    float* ob = out + (size_t)bi * CDIM * HW;
    for (int i = threadIdx.x; i < NTOK * CDIM; i += 256) {
        int c = i >> 6, n = i & 63;
        int iy = n >> 3, ix = n & 7;
        int hw = ((wy << 3) + iy) * IMGW + (wx << 3) + ix;
        ob[(size_t)c * HW + hw] = tile[n * 193 + c];
    }
}

// ---------------- launch ----------------
extern "C" void kernel_launch(void* const* d_in, const int* in_sizes, int n_in,
                              void* d_out, int out_size) {
    const float* x      = (const float*)d_in[0];
    const float* n1g    = (const float*)d_in[1];
    const float* n1b    = (const float*)d_in[2];
    const float* qkv_w  = (const float*)d_in[3];
    const float* qkv_b  = (const float*)d_in[4];
    const float* proj_w = (const float*)d_in[5];
    const float* proj_b = (const float*)d_in[6];
    const float* rpb    = (const float*)d_in[7];
    const float* temp   = (const float*)d_in[8];
    const float* n2g    = (const float*)d_in[9];
    const float* n2b    = (const float*)d_in[10];
    const float* fc1_w  = (const float*)d_in[11];
    const float* fc1_b  = (const float*)d_in[12];
    const float* fc2_w  = (const float*)d_in[13];
    const float* fc2_b  = (const float*)d_in[14];
    float* out = (float*)d_out;

    const int LN1_SMEM  = (64 * 193 + 128) * 4;
    const int TR_SMEM   = 64 * 193 * 4;
    cudaFuncSetAttribute(ln1_kernel,    cudaFuncAttributeMaxDynamicSharedMemorySize, LN1_SMEM);
    cudaFuncSetAttribute(attn_kernel,   cudaFuncAttributeMaxDynamicSharedMemorySize, ATTN_SMEM);
    cudaFuncSetAttribute(out_tr_kernel, cudaFuncAttributeMaxDynamicSharedMemorySize, TR_SMEM);
    cudaFuncSetAttribute(gemm_mma<0, 192, 3>, cudaFuncAttributeMaxDynamicSharedMemorySize, GSMEM3);
    cudaFuncSetAttribute(gemm_mma<1, 192, 1>, cudaFuncAttributeMaxDynamicSharedMemorySize, GSMEM1);
    cudaFuncSetAttribute(gemm_mma<2, 192, 1>, cudaFuncAttributeMaxDynamicSharedMemorySize, GSMEM1);
    cudaFuncSetAttribute(gemm_mma<3, 768, 1>, cudaFuncAttributeMaxDynamicSharedMemorySize, GSMEM1);

    wconv_kernel<<<(WTOT / 4 + 255) / 256, 256>>>(qkv_w, proj_w, fc1_w, fc2_w);
    ln1_kernel<<<NWIN, 256, LN1_SMEM>>>(x, n1g, n1b);
    gemm_mma<0, 192, 3><<<dim3(ROWS / 128, CH3 / 64), 256, GSMEM3>>>(qkv_b);
    attn_kernel<<<NWIN * HEADS, 256, ATTN_SMEM>>>(rpb, temp);
    gemm_mma<1, 192, 1><<<dim3(ROWS / 128, CDIM / 64), 256, GSMEM1>>>(proj_b);
    ln2_norm_kernel<<<ROWS / 8, 256>>>(n2g, n2b);
    gemm_mma<2, 192, 1><<<dim3(ROWS / 128, FF / 64), 256, GSMEM1>>>(fc1_b);
    gemm_mma<3, 768, 1><<<dim3(ROWS / 128, CDIM / 64), 256, GSMEM1>>>(fc2_b);
    out_tr_kernel<<<NWIN, 256, TR_SMEM>>>(out);
}